// round 1
// baseline (speedup 1.0000x reference)
#include <cuda_runtime.h>
#include <math.h>

#define N_STEPS 2048
#define N_ARMS 5000
#define HS 10
#define ARMS_PER_BLOCK 8

// Scratch (no cudaMalloc allowed): action table + eigen data
__device__ __align__(16) float g_act[2 * N_STEPS];
__device__ float g_c[HS];
__device__ float g_loglam[HS];

// ---------------------------------------------------------------------------
// Kernel 1: setup. One block, 256 threads.
//   h = relu(W1@target + b1)            (256 threads)
//   x0 = W2@h + b2                      (threads 0..9)
//   P^-1 via double Gauss-Jordan w/ partial pivoting (warp 0, lane=row)
//   c = P^-1 @ x0 ; loglam_i = log(1 - 0.01*exp(D_i))
// ---------------------------------------------------------------------------
__global__ void setup_kernel(const float* __restrict__ target,
                             const float* __restrict__ D,
                             const float* __restrict__ P,
                             const float* __restrict__ W1,
                             const float* __restrict__ b1,
                             const float* __restrict__ W2,
                             const float* __restrict__ b2) {
    __shared__ float h[256];
    __shared__ float x0[HS];
    __shared__ double aug[HS][2 * HS];

    int tid = threadIdx.x;
    float t0 = target[0], t1 = target[1];
    float v = W1[tid * 2] * t0 + W1[tid * 2 + 1] * t1 + b1[tid];
    h[tid] = v > 0.f ? v : 0.f;
    __syncthreads();

    if (tid < HS) {
        float acc = b2[tid];
        const float* w = W2 + tid * 256;
        #pragma unroll 8
        for (int j = 0; j < 256; j++) acc += w[j] * h[j];
        x0[tid] = acc;
        // init augmented [P | I] in double
        for (int c = 0; c < HS; c++) {
            aug[tid][c] = (double)P[tid * HS + c];
            aug[tid][HS + c] = (tid == c) ? 1.0 : 0.0;
        }
    }
    __syncthreads();

    if (tid < 32) {  // warp 0 only: Gauss-Jordan, lane i owns row i
        for (int k = 0; k < HS; k++) {
            if (tid == 0) {  // partial pivot: swap best row into k
                int r = k;
                double best = fabs(aug[k][k]);
                for (int i = k + 1; i < HS; i++) {
                    double m = fabs(aug[i][k]);
                    if (m > best) { best = m; r = i; }
                }
                if (r != k) {
                    for (int c = 0; c < 2 * HS; c++) {
                        double tmp = aug[k][c]; aug[k][c] = aug[r][c]; aug[r][c] = tmp;
                    }
                }
            }
            __syncwarp();
            if (tid == k) {
                double pinv = 1.0 / aug[k][k];
                for (int c = 0; c < 2 * HS; c++) aug[k][c] *= pinv;
            }
            __syncwarp();
            if (tid < HS && tid != k) {
                double f = aug[tid][k];
                for (int c = 0; c < 2 * HS; c++) aug[tid][c] -= f * aug[k][c];
            }
            __syncwarp();
        }
        if (tid < HS) {
            double acc = 0.0;
            for (int i = 0; i < HS; i++) acc += aug[tid][HS + i] * (double)x0[i];
            g_c[tid] = (float)acc;
            double lam = 1.0 - 0.01 * exp((double)D[tid]);
            g_loglam[tid] = (float)log(lam);
        }
    }
}

// ---------------------------------------------------------------------------
// Kernel 2: actions. 2048 threads over 16 blocks (parallel-in-time via
// eigendecomposition: hidden[t] = P * diag(lam^t) * c).
//   act[2t+k] = tanh(Wm[k,:] @ hidden[t] + bm[k])
// ---------------------------------------------------------------------------
__global__ void actions_kernel(const float* __restrict__ P,
                               const float* __restrict__ Wm,
                               const float* __restrict__ bm) {
    int t = blockIdx.x * blockDim.x + threadIdx.x;
    if (t >= N_STEPS) return;
    float tf = (float)t;
    float w[HS];
    #pragma unroll
    for (int i = 0; i < HS; i++)
        w[i] = g_c[i] * __expf(tf * g_loglam[i]);
    float u0 = bm[0], u1 = bm[1];
    #pragma unroll
    for (int j = 0; j < HS; j++) {
        float xj = 0.f;
        #pragma unroll
        for (int i = 0; i < HS; i++) xj += P[j * HS + i] * w[i];
        u0 += Wm[j] * xj;         // Wm[0, j]
        u1 += Wm[HS + j] * xj;    // Wm[1, j]
    }
    g_act[2 * t]     = tanhf(u0);
    g_act[2 * t + 1] = tanhf(u1);
}

// ---------------------------------------------------------------------------
// Kernel 3: stream. Memory-bound elementwise over 20.48M floats.
// out[arm*4096 + p] = (act[p] + 0.01*eps[arm*4096 + p]) * 15000
// 8 arms per block; 16KB action table staged in smem once per block.
// float4 everywhere; 8 independent global loads in flight per thread.
// ---------------------------------------------------------------------------
__global__ void stream_kernel(const float4* __restrict__ eps,
                              float4* __restrict__ out) {
    __shared__ float4 s_act[N_STEPS / 2];  // 1024 float4 = 4096 floats
    int tid = threadIdx.x;
    const float4* act4 = reinterpret_cast<const float4*>(g_act);
    #pragma unroll
    for (int k = 0; k < 4; k++)
        s_act[tid + 256 * k] = act4[tid + 256 * k];
    __syncthreads();

    size_t base = (size_t)blockIdx.x * (ARMS_PER_BLOCK * 1024);
    #pragma unroll
    for (int k = 0; k < 4; k++) {
        float4 a = s_act[tid + 256 * k];
        #pragma unroll
        for (int arm = 0; arm < ARMS_PER_BLOCK; arm++) {
            size_t idx = base + (size_t)arm * 1024 + tid + 256 * k;
            float4 e = eps[idx];
            float4 o;
            o.x = (a.x + 0.01f * e.x) * 15000.f;
            o.y = (a.y + 0.01f * e.y) * 15000.f;
            o.z = (a.z + 0.01f * e.z) * 15000.f;
            o.w = (a.w + 0.01f * e.w) * 15000.f;
            out[idx] = o;
        }
    }
}

extern "C" void kernel_launch(void* const* d_in, const int* in_sizes, int n_in,
                              void* d_out, int out_size) {
    const float* target = (const float*)d_in[0];
    const float* eps    = (const float*)d_in[1];
    const float* D      = (const float*)d_in[2];
    const float* P      = (const float*)d_in[3];
    const float* W1     = (const float*)d_in[4];
    const float* b1     = (const float*)d_in[5];
    const float* W2     = (const float*)d_in[6];
    const float* b2     = (const float*)d_in[7];
    const float* Wm     = (const float*)d_in[8];
    const float* bm     = (const float*)d_in[9];

    setup_kernel<<<1, 256>>>(target, D, P, W1, b1, W2, b2);
    actions_kernel<<<N_STEPS / 128, 128>>>(P, Wm, bm);
    stream_kernel<<<N_ARMS / ARMS_PER_BLOCK, 256>>>(
        (const float4*)eps, (float4*)d_out);
}

// round 2
// speedup vs baseline: 1.2559x; 1.2559x over previous
#include <cuda_runtime.h>
#include <math.h>

#define N_STEPS 2048
#define N_ARMS 5000
#define HS 10
#define ARMS_PER_BLOCK 8

// Scratch (no cudaMalloc allowed): action table + eigen data
__device__ __align__(16) float g_act[2 * N_STEPS];
__device__ float g_c[HS];
__device__ float g_loglam[HS];

// ---------------------------------------------------------------------------
// Kernel 1: setup. One block, 320 threads (10 warps). All fp32.
//   h = relu(W1@target + b1)                  (threads 0..255)
//   x0[w] = W2[w,:]@h + b2[w]                 (warp w, shuffle reduce)
//   solve P c = x0 via fp32 Gauss-Jordan on [P | x0] (warp 0, lane=row)
//   loglam_i = logf(1 - 0.01*expf(D_i))
// ---------------------------------------------------------------------------
__global__ void setup_kernel(const float* __restrict__ target,
                             const float* __restrict__ D,
                             const float* __restrict__ P,
                             const float* __restrict__ W1,
                             const float* __restrict__ b1,
                             const float* __restrict__ W2,
                             const float* __restrict__ b2) {
    __shared__ float h[256];
    __shared__ float aug[HS][HS + 1];  // [P | x0]

    int tid = threadIdx.x;
    int wid = tid >> 5;
    int lid = tid & 31;

    if (tid < 256) {
        float t0 = target[0], t1 = target[1];
        float v = W1[tid * 2] * t0 + W1[tid * 2 + 1] * t1 + b1[tid];
        h[tid] = v > 0.f ? v : 0.f;
    }
    // warp 0 loads P into aug while others compute h (independent)
    if (tid < HS * HS) {
        aug[tid / HS][tid % HS] = P[tid];
    }
    __syncthreads();

    // x0: warp w reduces W2 row w (8 elems/lane + shuffle tree)
    if (wid < HS) {
        const float* w2row = W2 + wid * 256;
        float acc = 0.f;
        #pragma unroll
        for (int j = lid; j < 256; j += 32) acc += w2row[j] * h[j];
        #pragma unroll
        for (int s = 16; s > 0; s >>= 1) acc += __shfl_down_sync(0xFFFFFFFFu, acc, s);
        if (lid == 0) aug[wid][HS] = acc + b2[wid];
    }
    __syncthreads();

    if (tid < 32) {  // warp 0: fp32 Gauss-Jordan solve, lane i owns row i
        for (int k = 0; k < HS; k++) {
            if (tid == 0) {  // partial pivot
                int r = k;
                float best = fabsf(aug[k][k]);
                for (int i = k + 1; i < HS; i++) {
                    float m = fabsf(aug[i][k]);
                    if (m > best) { best = m; r = i; }
                }
                if (r != k) {
                    #pragma unroll
                    for (int c = 0; c <= HS; c++) {
                        float tmp = aug[k][c]; aug[k][c] = aug[r][c]; aug[r][c] = tmp;
                    }
                }
            }
            __syncwarp();
            if (tid == k) {
                float pinv = 1.f / aug[k][k];
                #pragma unroll
                for (int c = 0; c <= HS; c++) aug[k][c] *= pinv;
            }
            __syncwarp();
            if (tid < HS && tid != k) {
                float f = aug[tid][k];
                #pragma unroll
                for (int c = 0; c <= HS; c++) aug[tid][c] -= f * aug[k][c];
            }
            __syncwarp();
        }
        if (tid < HS) {
            g_c[tid] = aug[tid][HS];
            g_loglam[tid] = logf(1.0f - 0.01f * expf(D[tid]));
        }
    }
}

// ---------------------------------------------------------------------------
// Kernel 2: actions. Parallel-in-time via eigendecomposition:
//   hidden[t] = P * diag(lam^t) * c ;  act[2t+k] = tanh(Wm[k,:]@hidden[t]+bm[k])
// ---------------------------------------------------------------------------
__global__ void actions_kernel(const float* __restrict__ P,
                               const float* __restrict__ Wm,
                               const float* __restrict__ bm) {
    int t = blockIdx.x * blockDim.x + threadIdx.x;
    if (t >= N_STEPS) return;
    float tf = (float)t;
    float w[HS];
    #pragma unroll
    for (int i = 0; i < HS; i++)
        w[i] = g_c[i] * __expf(tf * g_loglam[i]);
    float u0 = bm[0], u1 = bm[1];
    #pragma unroll
    for (int j = 0; j < HS; j++) {
        float xj = 0.f;
        #pragma unroll
        for (int i = 0; i < HS; i++) xj += P[j * HS + i] * w[i];
        u0 += Wm[j] * xj;         // Wm[0, j]
        u1 += Wm[HS + j] * xj;    // Wm[1, j]
    }
    g_act[2 * t]     = tanhf(u0);
    g_act[2 * t + 1] = tanhf(u1);
}

// ---------------------------------------------------------------------------
// Kernel 3: stream. Memory-bound elementwise over 20.48M floats.
// out[arm*4096 + p] = (act[p] + 0.01*eps[arm*4096 + p]) * 15000
// 8 arms/block; 16KB action table staged in smem; float4; streaming hints.
// ---------------------------------------------------------------------------
__global__ void stream_kernel(const float4* __restrict__ eps,
                              float4* __restrict__ out) {
    __shared__ float4 s_act[N_STEPS / 2];  // 1024 float4 = 4096 floats
    int tid = threadIdx.x;
    const float4* act4 = reinterpret_cast<const float4*>(g_act);
    #pragma unroll
    for (int k = 0; k < 4; k++)
        s_act[tid + 256 * k] = act4[tid + 256 * k];
    __syncthreads();

    size_t base = (size_t)blockIdx.x * (ARMS_PER_BLOCK * 1024);
    #pragma unroll
    for (int k = 0; k < 4; k++) {
        float4 a = s_act[tid + 256 * k];
        #pragma unroll
        for (int arm = 0; arm < ARMS_PER_BLOCK; arm++) {
            size_t idx = base + (size_t)arm * 1024 + tid + 256 * k;
            float4 e = __ldcs(&eps[idx]);
            float4 o;
            o.x = (a.x + 0.01f * e.x) * 15000.f;
            o.y = (a.y + 0.01f * e.y) * 15000.f;
            o.z = (a.z + 0.01f * e.z) * 15000.f;
            o.w = (a.w + 0.01f * e.w) * 15000.f;
            __stcs(&out[idx], o);
        }
    }
}

extern "C" void kernel_launch(void* const* d_in, const int* in_sizes, int n_in,
                              void* d_out, int out_size) {
    const float* target = (const float*)d_in[0];
    const float* eps    = (const float*)d_in[1];
    const float* D      = (const float*)d_in[2];
    const float* P      = (const float*)d_in[3];
    const float* W1     = (const float*)d_in[4];
    const float* b1     = (const float*)d_in[5];
    const float* W2     = (const float*)d_in[6];
    const float* b2     = (const float*)d_in[7];
    const float* Wm     = (const float*)d_in[8];
    const float* bm     = (const float*)d_in[9];

    setup_kernel<<<1, 320>>>(target, D, P, W1, b1, W2, b2);
    actions_kernel<<<N_STEPS / 128, 128>>>(P, Wm, bm);
    stream_kernel<<<N_ARMS / ARMS_PER_BLOCK, 256>>>(
        (const float4*)eps, (float4*)d_out);
}